// round 2
// baseline (speedup 1.0000x reference)
#include <cuda_runtime.h>

#define NN 100000
#define NE 1600000
#define NR 4
#define DD 64
#define EPSF 1e-10f

// ---------------- scratch (static __device__ — no runtime allocs) ----------------
__device__ __align__(16) float g_agg[(size_t)NN * NR * DD];   // 102.4 MB
__device__ float g_deg[NN * NR];                              // 1.6 MB
__device__ float g_wn[NE];                                    // 6.4 MB  (ew/(deg+eps))
__device__ __align__(16) float g_hidA[(size_t)NN * DD];       // hidden of layer 0
__device__ __align__(16) float g_hidB[(size_t)NN * DD];       // hidden of layer 1
__device__ __align__(16) float g_gatA[(size_t)NN * DD];       // gated of layer 0
__device__ __align__(16) float g_gatB[(size_t)NN * DD];       // gated of layer 1

// ---------------- helpers ----------------
__device__ __forceinline__ float sigf(float x) { return 1.0f / (1.0f + __expf(-x)); }

__device__ __forceinline__ unsigned long long pk2(float a, float b) {
    unsigned long long r;
    asm("mov.b64 %0, {%1, %2};" : "=l"(r) : "f"(a), "f"(b));
    return r;
}
__device__ __forceinline__ void upk2(unsigned long long v, float& a, float& b) {
    asm("mov.b64 {%0, %1}, %2;" : "=f"(a), "=f"(b) : "l"(v));
}
// packed fp32x2 FMA — 2x fma-pipe throughput vs scalar FFMA (ptxas never emits this from C++)
__device__ __forceinline__ unsigned long long fma2(unsigned long long a, unsigned long long b,
                                                   unsigned long long c) {
    unsigned long long d;
    asm("fma.rn.f32x2 %0, %1, %2, %3;" : "=l"(d) : "l"(a), "l"(b), "l"(c));
    return d;
}

// ---------------- setup kernels (once per launch; shared by all 3 layers) ----------------
__global__ void k_deg_acc(const float* __restrict__ ew, const int* __restrict__ dst,
                          const int* __restrict__ rel) {
    int e = blockIdx.x * blockDim.x + threadIdx.x;
    if (e >= NE) return;
    atomicAdd(&g_deg[dst[e] * NR + rel[e]], ew[e]);
}

__global__ void k_wnorm(const float* __restrict__ ew, const int* __restrict__ dst,
                        const int* __restrict__ rel) {
    int e = blockIdx.x * blockDim.x + threadIdx.x;
    if (e >= NE) return;
    g_wn[e] = ew[e] / (g_deg[dst[e] * NR + rel[e]] + EPSF);
}

__global__ void k_zero_agg() {
    size_t i = (size_t)blockIdx.x * blockDim.x + threadIdx.x;
    const size_t n4 = (size_t)NN * NR * DD / 4;
    float4 z = make_float4(0.f, 0.f, 0.f, 0.f);
    for (; i < n4; i += (size_t)gridDim.x * blockDim.x)
        reinterpret_cast<float4*>(g_agg)[i] = z;
}

// ---------------- edge scatter: 16 threads/edge, float4 gather + red.v4 ----------------
__global__ void k_scatter(int layer, const float* __restrict__ nf,
                          const int* __restrict__ src, const int* __restrict__ dst,
                          const int* __restrict__ rel) {
    int t = blockIdx.x * blockDim.x + threadIdx.x;   // 25.6M threads total
    int e = t >> 4;
    int c = t & 15;
    if (e >= NE) return;
    const float* cur = (layer == 0) ? nf : ((layer == 1) ? g_gatA : g_gatB);
    int s = src[e];
    int d = dst[e];
    int r = rel[e];
    float w = g_wn[e];
    float4 v = *reinterpret_cast<const float4*>(cur + (size_t)s * DD + c * 4);
    float4 m = make_float4(v.x * w, v.y * w, v.z * w, v.w * w);
    float* ap = g_agg + ((size_t)d * NR + r) * DD + c * 4;
    asm volatile("red.global.add.v4.f32 [%0], {%1, %2, %3, %4};"
                 :: "l"(ap), "f"(m.x), "f"(m.y), "f"(m.z), "f"(m.w)
                 : "memory");
}

// ---------------- fused RGCN-linear + sigmoid + highway, per 32-node tile ----------------
// block = 128 threads = 16 d-threads (4 outputs each) x 8 node-threads (4 nodes each)
__global__ void __launch_bounds__(128, 4)
k_node(int layer, const float* __restrict__ nf,
       const float* __restrict__ lin_w, const float* __restrict__ lin_b,
       const float* __restrict__ self_w, const float* __restrict__ self_b,
       const float* __restrict__ pw, const float* __restrict__ pb,
       const float* __restrict__ tw, const float* __restrict__ tb,
       float* __restrict__ dout) {
    __shared__ float upd_s[32][257];   // padded: row stride 257 -> conflict-free broadcast
    __shared__ float x_s[32][65];

    const float* cur  = (layer == 0) ? nf : ((layer == 1) ? g_gatA : g_gatB);
    const float* prev = (layer == 0) ? nf : ((layer == 1) ? g_hidA : g_hidB);
    float* hid_out = (layer == 0) ? g_hidA : g_hidB;
    float* gat_out = (layer == 0) ? g_gatA : ((layer == 1) ? g_gatB : dout);

    const int tid  = threadIdx.x;
    const int tile = blockIdx.x * 32;

    // stage upd (32 x 256) and x (32 x 64)
#pragma unroll
    for (int i = tid; i < 2048; i += 128) {
        int n = i >> 6, q = i & 63;
        float4 v = *reinterpret_cast<const float4*>(g_agg + (size_t)(tile + n) * 256 + q * 4);
        float* p = &upd_s[n][q * 4];
        p[0] = v.x; p[1] = v.y; p[2] = v.z; p[3] = v.w;
    }
#pragma unroll
    for (int i = tid; i < 512; i += 128) {
        int n = i >> 4, q = i & 15;
        float4 v = *reinterpret_cast<const float4*>(cur + (size_t)(tile + n) * DD + q * 4);
        float* p = &x_s[n][q * 4];
        p[0] = v.x; p[1] = v.y; p[2] = v.z; p[3] = v.w;
    }
    __syncthreads();

    const int dx = (tid & 15) * 4;   // first of 4 output features
    const int ny = (tid >> 4) * 4;   // first of 4 nodes

    const float* lw = lin_w + layer * (NR * DD * DD);
    const float* sw = self_w + layer * (DD * DD);

    unsigned long long acc[4][2];
    {
        float b0 = lin_b[layer * DD + dx + 0] + self_b[layer * DD + dx + 0];
        float b1 = lin_b[layer * DD + dx + 1] + self_b[layer * DD + dx + 1];
        float b2 = lin_b[layer * DD + dx + 2] + self_b[layer * DD + dx + 2];
        float b3 = lin_b[layer * DD + dx + 3] + self_b[layer * DD + dx + 3];
        unsigned long long p0 = pk2(b0, b1), p1 = pk2(b2, b3);
#pragma unroll
        for (int j = 0; j < 4; ++j) { acc[j][0] = p0; acc[j][1] = p1; }
    }

    // hidden = sigmoid(upd @ lin_w + x @ self_w + b)
#pragma unroll 4
    for (int k = 0; k < 256; ++k) {
        float4 wv = *reinterpret_cast<const float4*>(lw + k * DD + dx);
        unsigned long long w0 = pk2(wv.x, wv.y), w1 = pk2(wv.z, wv.w);
        float u0 = upd_s[ny + 0][k], u1 = upd_s[ny + 1][k];
        float u2 = upd_s[ny + 2][k], u3 = upd_s[ny + 3][k];
        unsigned long long uu0 = pk2(u0, u0), uu1 = pk2(u1, u1);
        unsigned long long uu2 = pk2(u2, u2), uu3 = pk2(u3, u3);
        acc[0][0] = fma2(uu0, w0, acc[0][0]); acc[0][1] = fma2(uu0, w1, acc[0][1]);
        acc[1][0] = fma2(uu1, w0, acc[1][0]); acc[1][1] = fma2(uu1, w1, acc[1][1]);
        acc[2][0] = fma2(uu2, w0, acc[2][0]); acc[2][1] = fma2(uu2, w1, acc[2][1]);
        acc[3][0] = fma2(uu3, w0, acc[3][0]); acc[3][1] = fma2(uu3, w1, acc[3][1]);
    }
#pragma unroll 4
    for (int k = 0; k < 64; ++k) {
        float4 wv = *reinterpret_cast<const float4*>(sw + k * DD + dx);
        unsigned long long w0 = pk2(wv.x, wv.y), w1 = pk2(wv.z, wv.w);
        float u0 = x_s[ny + 0][k], u1 = x_s[ny + 1][k];
        float u2 = x_s[ny + 2][k], u3 = x_s[ny + 3][k];
        unsigned long long uu0 = pk2(u0, u0), uu1 = pk2(u1, u1);
        unsigned long long uu2 = pk2(u2, u2), uu3 = pk2(u3, u3);
        acc[0][0] = fma2(uu0, w0, acc[0][0]); acc[0][1] = fma2(uu0, w1, acc[0][1]);
        acc[1][0] = fma2(uu1, w0, acc[1][0]); acc[1][1] = fma2(uu1, w1, acc[1][1]);
        acc[2][0] = fma2(uu2, w0, acc[2][0]); acc[2][1] = fma2(uu2, w1, acc[2][1]);
        acc[3][0] = fma2(uu3, w0, acc[3][0]); acc[3][1] = fma2(uu3, w1, acc[3][1]);
    }

    float h[4][4];
#pragma unroll
    for (int j = 0; j < 4; ++j) {
        upk2(acc[j][0], h[j][0], h[j][1]);
        upk2(acc[j][1], h[j][2], h[j][3]);
#pragma unroll
        for (int i = 0; i < 4; ++i) h[j][i] = sigf(h[j][i]);
    }

    __syncthreads();   // everyone is done reading upd_s / x_s

    // stage hidden into x_s; store hidden to global (needed as prev by next layer)
#pragma unroll
    for (int j = 0; j < 4; ++j) {
#pragma unroll
        for (int i = 0; i < 4; ++i) x_s[ny + j][dx + i] = h[j][i];
        if (layer < 2) {
            *reinterpret_cast<float4*>(hid_out + (size_t)(tile + ny + j) * DD + dx) =
                make_float4(h[j][0], h[j][1], h[j][2], h[j][3]);
        }
    }
    // stage prev into (reused) upd_s memory, row stride 65
    float* ps = &upd_s[0][0];
#pragma unroll
    for (int i = tid; i < 512; i += 128) {
        int n = i >> 4, q = i & 15;
        float4 v = *reinterpret_cast<const float4*>(prev + (size_t)(tile + n) * DD + q * 4);
        float* p = ps + n * 65 + q * 4;
        p[0] = v.x; p[1] = v.y; p[2] = v.z; p[3] = v.w;
    }
    __syncthreads();

    // highway: cat = [hidden, prev]; proj = relu(cat@pw + pb); gate = sig(cat@tw + tb)
    const float* pwl = pw + layer * (2 * DD * DD);
    const float* twl = tw + layer * (2 * DD * DD);
    unsigned long long aP[4][2], aG[4][2];
    {
        float p0 = pb[layer * DD + dx + 0], p1 = pb[layer * DD + dx + 1];
        float p2 = pb[layer * DD + dx + 2], p3 = pb[layer * DD + dx + 3];
        float t0 = tb[layer * DD + dx + 0], t1 = tb[layer * DD + dx + 1];
        float t2 = tb[layer * DD + dx + 2], t3 = tb[layer * DD + dx + 3];
        unsigned long long P0 = pk2(p0, p1), P1 = pk2(p2, p3);
        unsigned long long T0 = pk2(t0, t1), T1 = pk2(t2, t3);
#pragma unroll
        for (int j = 0; j < 4; ++j) { aP[j][0] = P0; aP[j][1] = P1; aG[j][0] = T0; aG[j][1] = T1; }
    }
#pragma unroll 2
    for (int k = 0; k < 64; ++k) {   // top half of cat: hidden
        float4 wp = *reinterpret_cast<const float4*>(pwl + k * DD + dx);
        float4 wt = *reinterpret_cast<const float4*>(twl + k * DD + dx);
        unsigned long long p0 = pk2(wp.x, wp.y), p1 = pk2(wp.z, wp.w);
        unsigned long long t0 = pk2(wt.x, wt.y), t1 = pk2(wt.z, wt.w);
#pragma unroll
        for (int j = 0; j < 4; ++j) {
            float hh = x_s[ny + j][k];
            unsigned long long uu = pk2(hh, hh);
            aP[j][0] = fma2(uu, p0, aP[j][0]);
            aP[j][1] = fma2(uu, p1, aP[j][1]);
            aG[j][0] = fma2(uu, t0, aG[j][0]);
            aG[j][1] = fma2(uu, t1, aG[j][1]);
        }
    }
#pragma unroll 2
    for (int k = 0; k < 64; ++k) {   // bottom half of cat: prev
        float4 wp = *reinterpret_cast<const float4*>(pwl + (64 + k) * DD + dx);
        float4 wt = *reinterpret_cast<const float4*>(twl + (64 + k) * DD + dx);
        unsigned long long p0 = pk2(wp.x, wp.y), p1 = pk2(wp.z, wp.w);
        unsigned long long t0 = pk2(wt.x, wt.y), t1 = pk2(wt.z, wt.w);
#pragma unroll
        for (int j = 0; j < 4; ++j) {
            float pv = ps[(ny + j) * 65 + k];
            unsigned long long uu = pk2(pv, pv);
            aP[j][0] = fma2(uu, p0, aP[j][0]);
            aP[j][1] = fma2(uu, p1, aP[j][1]);
            aG[j][0] = fma2(uu, t0, aG[j][0]);
            aG[j][1] = fma2(uu, t1, aG[j][1]);
        }
    }

    // gated = gate*relu(proj) + (1-gate)*hidden
#pragma unroll
    for (int j = 0; j < 4; ++j) {
        float P[4], G[4];
        upk2(aP[j][0], P[0], P[1]); upk2(aP[j][1], P[2], P[3]);
        upk2(aG[j][0], G[0], G[1]); upk2(aG[j][1], G[2], G[3]);
        float o[4];
#pragma unroll
        for (int i = 0; i < 4; ++i) {
            float g = sigf(G[i]);
            float p = fmaxf(P[i], 0.0f);
            o[i] = g * p + (1.0f - g) * h[j][i];
        }
        *reinterpret_cast<float4*>(gat_out + (size_t)(tile + ny + j) * DD + dx) =
            make_float4(o[0], o[1], o[2], o[3]);
    }
}

// ---------------- launch ----------------
extern "C" void kernel_launch(void* const* d_in, const int* in_sizes, int n_in,
                              void* d_out, int out_size) {
    const float* nf     = (const float*)d_in[0];
    const float* ew     = (const float*)d_in[1];
    const float* lin_w  = (const float*)d_in[2];
    const float* lin_b  = (const float*)d_in[3];
    const float* self_w = (const float*)d_in[4];
    const float* self_b = (const float*)d_in[5];
    const float* pw     = (const float*)d_in[6];
    const float* pb     = (const float*)d_in[7];
    const float* tw     = (const float*)d_in[8];
    const float* tb     = (const float*)d_in[9];
    const int* src      = (const int*)d_in[10];
    const int* dst      = (const int*)d_in[11];
    const int* rel      = (const int*)d_in[12];
    float* out = (float*)d_out;

    // degree + normalized edge weights: identical for all layers, compute once
    void* degp = nullptr;
    cudaGetSymbolAddress(&degp, g_deg);
    cudaMemsetAsync(degp, 0, sizeof(float) * NN * NR);
    k_deg_acc<<<(NE + 255) / 256, 256>>>(ew, dst, rel);
    k_wnorm<<<(NE + 255) / 256, 256>>>(ew, dst, rel);

    for (int L = 0; L < 3; ++L) {
        k_zero_agg<<<4096, 256>>>();
        k_scatter<<<(NE * 16) / 256, 256>>>(L, nf, src, dst, rel);
        k_node<<<NN / 32, 128>>>(L, nf, lin_w, lin_b, self_w, self_b,
                                 pw, pb, tw, tb, out);
    }
}

// round 9
// speedup vs baseline: 1.3985x; 1.3985x over previous
#include <cuda_runtime.h>

#define NN 100000
#define NE 1600000
#define NR 4
#define DD 64
#define NSEG (NN * NR)          // 400000 segments
#define EPSF 1e-10f

// ---------------- scratch (static __device__ — no runtime allocs) ----------------
__device__ __align__(16) float g_agg[(size_t)NSEG * DD];      // 102.4 MB
__device__ float g_deg[NSEG];
__device__ int   g_hist[NSEG];                                // per-seg edge count
__device__ int   g_offp[NSEG];                                // per-block partial excl scan
__device__ int   g_off[NSEG + 1];                             // final CSR offsets
__device__ int   g_cur[NSEG];                                 // build cursors
__device__ int   g_bs[512];                                   // block sums (391 used)
__device__ __align__(8) int2 g_epack[NE];                     // CSR: (src idx, w bits) per slot
__device__ __align__(16) float g_hidA[(size_t)NN * DD];
__device__ __align__(16) float g_hidB[(size_t)NN * DD];
__device__ __align__(16) float g_gatA[(size_t)NN * DD];
__device__ __align__(16) float g_gatB[(size_t)NN * DD];

// ---------------- helpers ----------------
__device__ __forceinline__ float sigf(float x) { return 1.0f / (1.0f + __expf(-x)); }

__device__ __forceinline__ unsigned long long pk2(float a, float b) {
    unsigned long long r;
    asm("mov.b64 %0, {%1, %2};" : "=l"(r) : "f"(a), "f"(b));
    return r;
}
__device__ __forceinline__ void upk2(unsigned long long v, float& a, float& b) {
    asm("mov.b64 {%0, %1}, %2;" : "=f"(a), "=f"(b) : "l"(v));
}
// packed fp32x2 FMA — 2x fma-pipe throughput vs scalar FFMA
__device__ __forceinline__ unsigned long long fma2(unsigned long long a, unsigned long long b,
                                                   unsigned long long c) {
    unsigned long long d;
    asm("fma.rn.f32x2 %0, %1, %2, %3;" : "=l"(d) : "l"(a), "l"(b), "l"(c));
    return d;
}

// ---------------- setup: deg + hist (fused) ----------------
__global__ void k_deg_hist(const float* __restrict__ ew, const int* __restrict__ dst,
                           const int* __restrict__ rel) {
    int e = blockIdx.x * blockDim.x + threadIdx.x;
    if (e >= NE) return;
    int seg = dst[e] * NR + rel[e];
    atomicAdd(&g_deg[seg], ew[e]);
    atomicAdd(&g_hist[seg], 1);
}

// ---------------- 3-kernel exclusive scan over g_hist (1024 elems / block) ----------
__global__ void k_scan1() {   // 391 blocks x 512 threads
    __shared__ int s[512];
    int t = threadIdx.x;
    int base = blockIdx.x * 1024;
    int i0 = base + 2 * t, i1 = i0 + 1;
    int a = (i0 < NSEG) ? g_hist[i0] : 0;
    int b = (i1 < NSEG) ? g_hist[i1] : 0;
    int pair = a + b;
    s[t] = pair;
    __syncthreads();
#pragma unroll
    for (int off = 1; off < 512; off <<= 1) {
        int v = s[t] + ((t >= off) ? s[t - off] : 0);
        __syncthreads();
        s[t] = v;
        __syncthreads();
    }
    int incl = s[t];
    int exp_ = incl - pair;
    if (i0 < NSEG) g_offp[i0] = exp_;
    if (i1 < NSEG) g_offp[i1] = exp_ + a;
    if (t == 511) g_bs[blockIdx.x] = incl;
}

__global__ void k_scan2() {   // 1 block x 512 threads over 391 block sums
    __shared__ int s[512];
    int t = threadIdx.x;
    int v0 = (t < 391) ? g_bs[t] : 0;
    s[t] = v0;
    __syncthreads();
#pragma unroll
    for (int off = 1; off < 512; off <<= 1) {
        int v = s[t] + ((t >= off) ? s[t - off] : 0);
        __syncthreads();
        s[t] = v;
        __syncthreads();
    }
    g_bs[t] = s[t] - v0;   // exclusive
}

__global__ void k_scan3() {
    int i = blockIdx.x * blockDim.x + threadIdx.x;
    if (i >= NSEG) return;
    int o = g_offp[i] + g_bs[i >> 10];
    g_off[i] = o;
    g_cur[i] = o;
    if (i == 0) g_off[NSEG] = NE;
}

// build CSR; normalized weight computed inline (deg is final by now)
__global__ void k_build(const float* __restrict__ ew, const int* __restrict__ src,
                        const int* __restrict__ dst, const int* __restrict__ rel) {
    int e = blockIdx.x * blockDim.x + threadIdx.x;
    if (e >= NE) return;
    int seg = dst[e] * NR + rel[e];
    int pos = atomicAdd(&g_cur[seg], 1);
    float w = ew[e] / (g_deg[seg] + EPSF);
    g_epack[pos] = make_int2(src[e], __float_as_int(w));
}

// ---------------- segmented-sum aggregation (no atomics, no zeroing) -------------
// 16 threads per segment; thread c accumulates floats [4c..4c+3] over the range.
// All 16 lanes load the same packed (idx, w) record — uniform address, one
// 8B sector broadcast per group; keeps the per-edge chain LDG.64 -> LDG.128 -> FFMA.
__global__ void __launch_bounds__(256, 8) k_agg(int layer, const float* __restrict__ nf) {
    int t = blockIdx.x * blockDim.x + threadIdx.x;    // NSEG*16 threads
    int seg = t >> 4;
    int c = t & 15;
    if (seg >= NSEG) return;
    const float* cur = (layer == 0) ? nf : ((layer == 1) ? g_gatA : g_gatB);
    int beg = g_off[seg];
    int end = g_off[seg + 1];
    float4 acc = make_float4(0.f, 0.f, 0.f, 0.f);
    for (int i = beg; i < end; ++i) {
        int2 rec = g_epack[i];
        float w = __int_as_float(rec.y);
        float4 v = *reinterpret_cast<const float4*>(cur + (size_t)rec.x * DD + c * 4);
        acc.x += w * v.x; acc.y += w * v.y; acc.z += w * v.z; acc.w += w * v.w;
    }
    *reinterpret_cast<float4*>(g_agg + (size_t)seg * DD + c * 4) = acc;
}

// ---------------- fused RGCN-linear + sigmoid + highway, per 32-node tile --------
// block = 128 threads = 16 d-threads (4 feats) x 8 node-threads (4 nodes)
#define UPD_STRIDE 260
#define X_STRIDE 68
__global__ void __launch_bounds__(128, 5)
k_node(int layer, const float* __restrict__ nf,
       const float* __restrict__ lin_w, const float* __restrict__ lin_b,
       const float* __restrict__ self_w, const float* __restrict__ self_b,
       const float* __restrict__ pw, const float* __restrict__ pb,
       const float* __restrict__ tw, const float* __restrict__ tb,
       float* __restrict__ dout) {
    __shared__ float upd_s[32 * UPD_STRIDE];  // 32 x 260 floats (16B-aligned rows)
    __shared__ float x_s[32 * X_STRIDE];      // 32 x 68

    const float* cur  = (layer == 0) ? nf : ((layer == 1) ? g_gatA : g_gatB);
    const float* prev = (layer == 0) ? nf : ((layer == 1) ? g_hidA : g_hidB);
    float* hid_out = (layer == 0) ? g_hidA : g_hidB;
    float* gat_out = (layer == 0) ? g_gatA : ((layer == 1) ? g_gatB : dout);

    const int tid  = threadIdx.x;
    const int tile = blockIdx.x * 32;

    // stage upd (32 x 256) and x (32 x 64) — float4 in, float4 out
#pragma unroll
    for (int i = tid; i < 2048; i += 128) {
        int n = i >> 6, q = (i & 63) * 4;
        float4 v = *reinterpret_cast<const float4*>(g_agg + (size_t)(tile + n) * 256 + q);
        *reinterpret_cast<float4*>(&upd_s[n * UPD_STRIDE + q]) = v;
    }
#pragma unroll
    for (int i = tid; i < 512; i += 128) {
        int n = i >> 4, q = (i & 15) * 4;
        float4 v = *reinterpret_cast<const float4*>(cur + (size_t)(tile + n) * DD + q);
        *reinterpret_cast<float4*>(&x_s[n * X_STRIDE + q]) = v;
    }
    __syncthreads();

    const int dx = (tid & 15) * 4;
    const int ny = (tid >> 4) * 4;

    const float* lw = lin_w + layer * (NR * DD * DD);
    const float* sw = self_w + layer * (DD * DD);

    unsigned long long acc[4][2];
    {
        float b0 = lin_b[layer * DD + dx + 0] + self_b[layer * DD + dx + 0];
        float b1 = lin_b[layer * DD + dx + 1] + self_b[layer * DD + dx + 1];
        float b2 = lin_b[layer * DD + dx + 2] + self_b[layer * DD + dx + 2];
        float b3 = lin_b[layer * DD + dx + 3] + self_b[layer * DD + dx + 3];
        unsigned long long p0 = pk2(b0, b1), p1 = pk2(b2, b3);
#pragma unroll
        for (int j = 0; j < 4; ++j) { acc[j][0] = p0; acc[j][1] = p1; }
    }

    // hidden = sigmoid(upd @ lin_w + x @ self_w + b) — k in chunks of 4, float4 LDS
#pragma unroll 2
    for (int kc = 0; kc < 64; ++kc) {
        int k = kc * 4;
        float4 wv[4];
#pragma unroll
        for (int i = 0; i < 4; ++i)
            wv[i] = *reinterpret_cast<const float4*>(lw + (k + i) * DD + dx);
        float4 uv[4];
#pragma unroll
        for (int j = 0; j < 4; ++j)
            uv[j] = *reinterpret_cast<const float4*>(&upd_s[(ny + j) * UPD_STRIDE + k]);
#pragma unroll
        for (int i = 0; i < 4; ++i) {
            unsigned long long w0 = pk2(wv[i].x, wv[i].y), w1 = pk2(wv[i].z, wv[i].w);
            float u0 = (i == 0) ? uv[0].x : (i == 1) ? uv[0].y : (i == 2) ? uv[0].z : uv[0].w;
            float u1 = (i == 0) ? uv[1].x : (i == 1) ? uv[1].y : (i == 2) ? uv[1].z : uv[1].w;
            float u2 = (i == 0) ? uv[2].x : (i == 1) ? uv[2].y : (i == 2) ? uv[2].z : uv[2].w;
            float u3 = (i == 0) ? uv[3].x : (i == 1) ? uv[3].y : (i == 2) ? uv[3].z : uv[3].w;
            unsigned long long uu0 = pk2(u0, u0), uu1 = pk2(u1, u1);
            unsigned long long uu2 = pk2(u2, u2), uu3 = pk2(u3, u3);
            acc[0][0] = fma2(uu0, w0, acc[0][0]); acc[0][1] = fma2(uu0, w1, acc[0][1]);
            acc[1][0] = fma2(uu1, w0, acc[1][0]); acc[1][1] = fma2(uu1, w1, acc[1][1]);
            acc[2][0] = fma2(uu2, w0, acc[2][0]); acc[2][1] = fma2(uu2, w1, acc[2][1]);
            acc[3][0] = fma2(uu3, w0, acc[3][0]); acc[3][1] = fma2(uu3, w1, acc[3][1]);
        }
    }
#pragma unroll 2
    for (int kc = 0; kc < 16; ++kc) {
        int k = kc * 4;
        float4 wv[4];
#pragma unroll
        for (int i = 0; i < 4; ++i)
            wv[i] = *reinterpret_cast<const float4*>(sw + (k + i) * DD + dx);
        float4 uv[4];
#pragma unroll
        for (int j = 0; j < 4; ++j)
            uv[j] = *reinterpret_cast<const float4*>(&x_s[(ny + j) * X_STRIDE + k]);
#pragma unroll
        for (int i = 0; i < 4; ++i) {
            unsigned long long w0 = pk2(wv[i].x, wv[i].y), w1 = pk2(wv[i].z, wv[i].w);
            float u0 = (i == 0) ? uv[0].x : (i == 1) ? uv[0].y : (i == 2) ? uv[0].z : uv[0].w;
            float u1 = (i == 0) ? uv[1].x : (i == 1) ? uv[1].y : (i == 2) ? uv[1].z : uv[1].w;
            float u2 = (i == 0) ? uv[2].x : (i == 1) ? uv[2].y : (i == 2) ? uv[2].z : uv[2].w;
            float u3 = (i == 0) ? uv[3].x : (i == 1) ? uv[3].y : (i == 2) ? uv[3].z : uv[3].w;
            unsigned long long uu0 = pk2(u0, u0), uu1 = pk2(u1, u1);
            unsigned long long uu2 = pk2(u2, u2), uu3 = pk2(u3, u3);
            acc[0][0] = fma2(uu0, w0, acc[0][0]); acc[0][1] = fma2(uu0, w1, acc[0][1]);
            acc[1][0] = fma2(uu1, w0, acc[1][0]); acc[1][1] = fma2(uu1, w1, acc[1][1]);
            acc[2][0] = fma2(uu2, w0, acc[2][0]); acc[2][1] = fma2(uu2, w1, acc[2][1]);
            acc[3][0] = fma2(uu3, w0, acc[3][0]); acc[3][1] = fma2(uu3, w1, acc[3][1]);
        }
    }

    float h[4][4];
#pragma unroll
    for (int j = 0; j < 4; ++j) {
        upk2(acc[j][0], h[j][0], h[j][1]);
        upk2(acc[j][1], h[j][2], h[j][3]);
#pragma unroll
        for (int i = 0; i < 4; ++i) h[j][i] = sigf(h[j][i]);
    }

    __syncthreads();   // done reading upd_s / x_s

    // hidden into x_s; hidden to global (next layer's prev); prev into upd_s region
#pragma unroll
    for (int j = 0; j < 4; ++j) {
        *reinterpret_cast<float4*>(&x_s[(ny + j) * X_STRIDE + dx]) =
            make_float4(h[j][0], h[j][1], h[j][2], h[j][3]);
        if (layer < 2) {
            *reinterpret_cast<float4*>(hid_out + (size_t)(tile + ny + j) * DD + dx) =
                make_float4(h[j][0], h[j][1], h[j][2], h[j][3]);
        }
    }
    float* ps = upd_s;   // reuse, stride X_STRIDE
#pragma unroll
    for (int i = tid; i < 512; i += 128) {
        int n = i >> 4, q = (i & 15) * 4;
        float4 v = *reinterpret_cast<const float4*>(prev + (size_t)(tile + n) * DD + q);
        *reinterpret_cast<float4*>(&ps[n * X_STRIDE + q]) = v;
    }
    __syncthreads();

    // highway
    const float* pwl = pw + layer * (2 * DD * DD);
    const float* twl = tw + layer * (2 * DD * DD);
    unsigned long long aP[4][2], aG[4][2];
    {
        float p0 = pb[layer * DD + dx + 0], p1 = pb[layer * DD + dx + 1];
        float p2 = pb[layer * DD + dx + 2], p3 = pb[layer * DD + dx + 3];
        float t0 = tb[layer * DD + dx + 0], t1 = tb[layer * DD + dx + 1];
        float t2 = tb[layer * DD + dx + 2], t3 = tb[layer * DD + dx + 3];
        unsigned long long P0 = pk2(p0, p1), P1 = pk2(p2, p3);
        unsigned long long T0 = pk2(t0, t1), T1 = pk2(t2, t3);
#pragma unroll
        for (int j = 0; j < 4; ++j) { aP[j][0] = P0; aP[j][1] = P1; aG[j][0] = T0; aG[j][1] = T1; }
    }
#pragma unroll 2
    for (int kc = 0; kc < 16; ++kc) {     // top half of cat: hidden (in x_s)
        int k = kc * 4;
        float4 uv[4];
#pragma unroll
        for (int j = 0; j < 4; ++j)
            uv[j] = *reinterpret_cast<const float4*>(&x_s[(ny + j) * X_STRIDE + k]);
#pragma unroll
        for (int i = 0; i < 4; ++i) {
            float4 wp = *reinterpret_cast<const float4*>(pwl + (k + i) * DD + dx);
            float4 wt = *reinterpret_cast<const float4*>(twl + (k + i) * DD + dx);
            unsigned long long p0 = pk2(wp.x, wp.y), p1 = pk2(wp.z, wp.w);
            unsigned long long t0 = pk2(wt.x, wt.y), t1 = pk2(wt.z, wt.w);
#pragma unroll
            for (int j = 0; j < 4; ++j) {
                float hh = (i == 0) ? uv[j].x : (i == 1) ? uv[j].y : (i == 2) ? uv[j].z : uv[j].w;
                unsigned long long uu = pk2(hh, hh);
                aP[j][0] = fma2(uu, p0, aP[j][0]);
                aP[j][1] = fma2(uu, p1, aP[j][1]);
                aG[j][0] = fma2(uu, t0, aG[j][0]);
                aG[j][1] = fma2(uu, t1, aG[j][1]);
            }
        }
    }
#pragma unroll 2
    for (int kc = 0; kc < 16; ++kc) {     // bottom half of cat: prev (in ps)
        int k = kc * 4;
        float4 uv[4];
#pragma unroll
        for (int j = 0; j < 4; ++j)
            uv[j] = *reinterpret_cast<const float4*>(&ps[(ny + j) * X_STRIDE + k]);
#pragma unroll
        for (int i = 0; i < 4; ++i) {
            float4 wp = *reinterpret_cast<const float4*>(pwl + (64 + k + i) * DD + dx);
            float4 wt = *reinterpret_cast<const float4*>(twl + (64 + k + i) * DD + dx);
            unsigned long long p0 = pk2(wp.x, wp.y), p1 = pk2(wp.z, wp.w);
            unsigned long long t0 = pk2(wt.x, wt.y), t1 = pk2(wt.z, wt.w);
#pragma unroll
            for (int j = 0; j < 4; ++j) {
                float pv = (i == 0) ? uv[j].x : (i == 1) ? uv[j].y : (i == 2) ? uv[j].z : uv[j].w;
                unsigned long long uu = pk2(pv, pv);
                aP[j][0] = fma2(uu, p0, aP[j][0]);
                aP[j][1] = fma2(uu, p1, aP[j][1]);
                aG[j][0] = fma2(uu, t0, aG[j][0]);
                aG[j][1] = fma2(uu, t1, aG[j][1]);
            }
        }
    }

    // gated = gate*relu(proj) + (1-gate)*hidden
#pragma unroll
    for (int j = 0; j < 4; ++j) {
        float P[4], G[4];
        upk2(aP[j][0], P[0], P[1]); upk2(aP[j][1], P[2], P[3]);
        upk2(aG[j][0], G[0], G[1]); upk2(aG[j][1], G[2], G[3]);
        float o[4];
#pragma unroll
        for (int i = 0; i < 4; ++i) {
            float g = sigf(G[i]);
            float p = fmaxf(P[i], 0.0f);
            o[i] = g * p + (1.0f - g) * h[j][i];
        }
        *reinterpret_cast<float4*>(gat_out + (size_t)(tile + ny + j) * DD + dx) =
            make_float4(o[0], o[1], o[2], o[3]);
    }
}

// ---------------- launch ----------------
extern "C" void kernel_launch(void* const* d_in, const int* in_sizes, int n_in,
                              void* d_out, int out_size) {
    const float* nf     = (const float*)d_in[0];
    const float* ew     = (const float*)d_in[1];
    const float* lin_w  = (const float*)d_in[2];
    const float* lin_b  = (const float*)d_in[3];
    const float* self_w = (const float*)d_in[4];
    const float* self_b = (const float*)d_in[5];
    const float* pw     = (const float*)d_in[6];
    const float* pb     = (const float*)d_in[7];
    const float* tw     = (const float*)d_in[8];
    const float* tb     = (const float*)d_in[9];
    const int* src      = (const int*)d_in[10];
    const int* dst      = (const int*)d_in[11];
    const int* rel      = (const int*)d_in[12];
    float* out = (float*)d_out;

    void* p = nullptr;
    cudaGetSymbolAddress(&p, g_deg);
    cudaMemsetAsync(p, 0, sizeof(float) * NSEG);
    cudaGetSymbolAddress(&p, g_hist);
    cudaMemsetAsync(p, 0, sizeof(int) * NSEG);

    // degree + hist + CSR build with inline weight normalization (layer-invariant)
    k_deg_hist<<<(NE + 255) / 256, 256>>>(ew, dst, rel);
    k_scan1<<<(NSEG + 1023) / 1024, 512>>>();
    k_scan2<<<1, 512>>>();
    k_scan3<<<(NSEG + 255) / 256, 256>>>();
    k_build<<<(NE + 255) / 256, 256>>>(ew, src, dst, rel);

    for (int L = 0; L < 3; ++L) {
        k_agg<<<(NSEG * 16 + 255) / 256, 256>>>(L, nf);
        k_node<<<NN / 32, 128>>>(L, nf, lin_w, lin_b, self_w, self_b,
                                 pw, pb, tw, tb, out);
    }
}